// round 13
// baseline (speedup 1.0000x reference)
#include <cuda_runtime.h>
#include <cstdint>

// Problem constants (fixed by the reference)
#define B_ 16
#define H_ 100
#define W_ 100
#define C_ 256
#define R_ 128
#define P_ 7
#define CELLS (P_ * P_)   // 49

typedef unsigned long long ULL;

// 256-bit global load (sm_100+, PTX 8.8): 4 x b64 = 32 bytes per lane.
__device__ __forceinline__ void ldg256(ULL& x0, ULL& x1, ULL& x2, ULL& x3,
                                       const void* p)
{
    asm("ld.global.nc.v4.b64 {%0,%1,%2,%3}, [%4];"
        : "=l"(x0), "=l"(x1), "=l"(x2), "=l"(x3) : "l"(p));
}

// 256-bit streaming global store.
__device__ __forceinline__ void stg256(void* p, ULL x0, ULL x1, ULL x2, ULL x3)
{
    asm volatile("st.global.cs.v4.b64 [%0], {%1,%2,%3,%4};"
                 :: "l"(p), "l"(x0), "l"(x1), "l"(x2), "l"(x3) : "memory");
}

// Packed f32x2 fused multiply-add: d = a*b + c elementwise on 2 packed fp32.
__device__ __forceinline__ ULL fma2(ULL a, ULL b, ULL c)
{
    ULL d;
    asm("fma.rn.f32x2 %0, %1, %2, %3;" : "=l"(d) : "l"(a), "l"(b), "l"(c));
    return d;
}

__device__ __forceinline__ ULL pack2(float f)
{
    ULL d;
    asm("mov.b64 %0, {%1, %1};" : "=l"(d) : "f"(f));
    return d;
}

// lerp on packed pairs: r = p*(1-f) + q*f  ==  fma(q, f, fma(p, -f, p))
__device__ __forceinline__ ULL lerp2(ULL p, ULL q, ULL f2, ULL nf2)
{
    return fma2(q, f2, fma2(p, nf2, p));
}

// ONE CTA per ROI, 224 threads = 7 warps. Warp w = pooling row py=w, sweeping
// px=0..6; each lane covers 8 channels via 256-bit loads/stores, so ONE warp
// covers all 256 channels of a cell. Per cell: 4 LDG.256 + 1 STG.256 + 12
// packed f32x2 FMAs — about half the instructions and half the scoreboard
// waits per byte of the LDG.128 variants (R3-R12, all ~35us). Row mapping
// keeps a warp's 28 corner loads on two feature rows for L1 reuse.
__global__ __launch_bounds__(224, 5) void roi_pool_kernel(
    const float* __restrict__ fm,   // [B, H, W, C]
    const int*   __restrict__ rois, // [B, R, 4]  (x, y, h, w)
    float*       __restrict__ out)  // [B, R, P, P, C]
{
    __shared__ int4   s_off[CELLS];   // float-unit offsets of the 4 corners
    __shared__ float2 s_fr[CELLS];    // (fx, fy)

    const int roi_idx = blockIdx.x;        // b*R + r
    const int b = roi_idx >> 7;            // R_ = 128
    const int tid = threadIdx.x;

    if (tid < CELLS) {
        const int4 roi = __ldg((const int4*)(rois + (size_t)roi_idx * 4));
        const int x = roi.x, y = roi.y, h = roi.z, w = roi.w;

        const int py = tid / P_;
        const int px = tid - py * P_;

        // y axis: src = (py+0.5)/P * h - 0.5, clipped to [0, h-1]
        const float hf = (float)h;
        float sy = ((float)py + 0.5f) * (1.0f / P_) * hf - 0.5f;
        sy = fminf(fmaxf(sy, 0.0f), hf - 1.0f);
        int   y0 = (int)floorf(sy);
        const float fy = sy - (float)y0;
        y0 += y;
        const int y1 = min(y0 + 1, y + h - 1);

        // x axis
        const float wf = (float)w;
        float sx = ((float)px + 0.5f) * (1.0f / P_) * wf - 0.5f;
        sx = fminf(fmaxf(sx, 0.0f), wf - 1.0f);
        int   x0 = (int)floorf(sx);
        const float fx = sx - (float)x0;
        x0 += x;
        const int x1 = min(x0 + 1, x + w - 1);

        // offsets in float units
        s_off[tid] = make_int4((y0 * W_ + x0) * C_,
                               (y0 * W_ + x1) * C_,
                               (y1 * W_ + x0) * C_,
                               (y1 * W_ + x1) * C_);
        s_fr[tid] = make_float2(fx, fy);
    }
    __syncthreads();

    const int wrp = tid >> 5;       // warp = pooling row py (0..6)
    const int ct  = tid & 31;       // lane = 8-channel group (0..31)

    const float* base  = fm + (size_t)b * (H_ * W_ * C_) + ct * 8;
    float*       obase = out + (size_t)roi_idx * (CELLS * C_) + ct * 8;

    const int cell0 = wrp * P_;

    int4   off = s_off[cell0];
    float2 fr  = s_fr[cell0];

    #pragma unroll
    for (int px = 0; px < P_; px++) {
        const int cell = cell0 + px;

        // Prefetch next tuple so the LDS sits off the critical path.
        int4   noff;
        float2 nfr;
        if (px < P_ - 1) {
            noff = s_off[cell + 1];
            nfr  = s_fr[cell + 1];
        }

        // 4 corners x 32B per lane, all four 256-bit loads in flight.
        ULL a0, a1, a2, a3, b0, b1, b2, b3;
        ULL c0, c1, c2, c3, d0, d1, d2, d3;
        ldg256(a0, a1, a2, a3, base + off.x);
        ldg256(b0, b1, b2, b3, base + off.y);
        ldg256(c0, c1, c2, c3, base + off.z);
        ldg256(d0, d1, d2, d3, base + off.w);

        const ULL fx2  = pack2(fr.x);
        const ULL nfx2 = pack2(-fr.x);
        const ULL fy2  = pack2(fr.y);
        const ULL nfy2 = pack2(-fr.y);

        const ULL t0 = lerp2(a0, b0, fx2, nfx2);
        const ULL t1 = lerp2(a1, b1, fx2, nfx2);
        const ULL t2 = lerp2(a2, b2, fx2, nfx2);
        const ULL t3 = lerp2(a3, b3, fx2, nfx2);
        const ULL u0 = lerp2(c0, d0, fx2, nfx2);
        const ULL u1 = lerp2(c1, d1, fx2, nfx2);
        const ULL u2 = lerp2(c2, d2, fx2, nfx2);
        const ULL u3 = lerp2(c3, d3, fx2, nfx2);

        const ULL o0 = lerp2(t0, u0, fy2, nfy2);
        const ULL o1 = lerp2(t1, u1, fy2, nfy2);
        const ULL o2 = lerp2(t2, u2, fy2, nfy2);
        const ULL o3 = lerp2(t3, u3, fy2, nfy2);

        stg256(obase + (size_t)cell * C_, o0, o1, o2, o3);

        if (px < P_ - 1) { off = noff; fr = nfr; }
    }
}

extern "C" void kernel_launch(void* const* d_in, const int* in_sizes, int n_in,
                              void* d_out, int out_size)
{
    const float* fm   = (const float*)d_in[0];
    const int*   rois = (const int*)d_in[1];
    float*       out  = (float*)d_out;

    roi_pool_kernel<<<B_ * R_, 224>>>(fm, rois, out);
}